// round 12
// baseline (speedup 1.0000x reference)
#include <cuda_runtime.h>
#include <cuda_fp16.h>
#include <math.h>
#include <stdint.h>

// Problem constants
#define BB   4
#define SS   4096
#define DD   1024
#define HH   16
#define MR   (BB*SS)          // 16384 rows
#define SEG  128
#define NSEG (SS/SEG)         // 32

#define NST  4                // pipeline stages
#define STB  24576            // bytes per stage (A 16KB + B 8KB)
#define BOFF 16384u           // B offset within stage
#define GEMM_SMEM (NST*STB)   // 96 KB

// ---------------- scratch (static device globals) ------------------------
__device__ float  g_att[(size_t)BB*SS*HH];
__device__ float  g_v[(size_t)MR*DD];          // v (fp32, pre-scan)
__device__ float  g_seg[(size_t)BB*NSEG*DD];
__device__ float  g_vb [(size_t)BB*DD];
__device__ __half g_in_h[(size_t)MR*DD];       // inputs (half)
__device__ __half g_attn_h[(size_t)MR*DD];     // attn_out (half)
__device__ __half g_h1h[(size_t)MR*DD];        // ff1 hidden (half)
__device__ __half g_valTh[(size_t)DD*DD];
__device__ __half g_f1tTh[(size_t)DD*DD];
__device__ __half g_t1h [(size_t)DD*DD];
__device__ __half g_ff2Th[(size_t)DD*DD];
__device__ __half g_operh[(size_t)DD*DD];
__device__ __half g_owTh[(size_t)DD*DD];

// =================== helpers =============================================
__device__ __forceinline__ uint32_t smem_u32(const void* p) {
    uint32_t a;
    asm("{ .reg .u64 t; cvta.to.shared.u64 t, %1; cvt.u32.u64 %0, t; }"
        : "=r"(a) : "l"(p));
    return a;
}
__device__ __forceinline__ void cp16(uint32_t s, const void* g) {
    asm volatile("cp.async.cg.shared.global [%0], [%1], 16;"
                 :: "r"(s), "l"(g) : "memory");
}
__device__ __forceinline__ void cp_commit() {
    asm volatile("cp.async.commit_group;" ::: "memory");
}
template<int N>
__device__ __forceinline__ void cp_wait() {
    asm volatile("cp.async.wait_group %0;" :: "n"(N) : "memory");
}
__device__ __forceinline__ void ldm_x4(uint32_t* r, uint32_t addr) {
    asm volatile("ldmatrix.sync.aligned.m8n8.x4.shared.b16 {%0,%1,%2,%3}, [%4];"
                 : "=r"(r[0]), "=r"(r[1]), "=r"(r[2]), "=r"(r[3]) : "r"(addr));
}
__device__ __forceinline__ void mma16(float* d, const uint32_t* a, const uint32_t* b) {
    asm volatile(
        "mma.sync.aligned.m16n8k16.row.col.f32.f16.f16.f32 "
        "{%0,%1,%2,%3}, {%4,%5,%6,%7}, {%8,%9}, {%0,%1,%2,%3};"
        : "+f"(d[0]), "+f"(d[1]), "+f"(d[2]), "+f"(d[3])
        : "r"(a[0]), "r"(a[1]), "r"(a[2]), "r"(a[3]), "r"(b[0]), "r"(b[1]));
}
__device__ __forceinline__ uint32_t pack_h2(float a, float b) {
    __half2 h = __floats2half2_rn(a, b);
    return *reinterpret_cast<uint32_t*>(&h);
}
// 64B-row swizzle: chunk (16B) index XOR'd by (row>>1)&3
__device__ __forceinline__ uint32_t sw64(int row, int ch) {
    return (uint32_t)(row * 64 + ((ch ^ ((row >> 1) & 3)) << 4));
}

// =================== fp16 mma.sync GEMM, 256x128 tile ====================
// C[m,n] = sum_k A1[m,k]*B1[n,k] (+ A2[m,k]*B2[n,k] if A2), K=1024 per pair.
// MODE 0: fp32 out              MODE 1: half out
// MODE 2: half(relu(acc + aux2[(row>>12)*DD+col]))
// MODE 3: fp32: acc + aux1[row*DD+col] + aux2[col]
// MODE 4: fp32 out + per-segment column sums -> aux1 (tile = 2 segments)
template<int MODE>
__global__ void __launch_bounds__(256, 1)
gemm_mma(const __half* __restrict__ A1, const __half* __restrict__ B1,
         const __half* __restrict__ A2, const __half* __restrict__ B2,
         void* __restrict__ Cv,
         float* __restrict__ aux1, const float* __restrict__ aux2) {
    extern __shared__ char sm[];
    const uint32_t sbase = smem_u32(sm);
    const int tid = threadIdx.x, lane = tid & 31, wid = tid >> 5;
    const int wm = (wid & 3) * 64, wn = (wid >> 2) * 64;
    const int m0 = blockIdx.y * 256, n0 = blockIdx.x * 128;
    const int r4 = lane >> 2, l4 = lane & 3;
    const int nch = A2 ? 64 : 32;   // chunks of K=32 halves

    // ldmatrix per-lane row/parity
    const int a_rlo = lane & 15;
    const int a_hb  = lane >> 4;
    const int b_rlo = (lane & 7) + ((lane >> 4) & 1) * 8;
    const int b_hb  = (lane >> 3) & 1;

    // cp.async mapping
    const int brow = tid & 127;
    const int bc0  = (tid >> 7) * 2;

    float acc[4][8][4];
    #pragma unroll
    for (int i = 0; i < 4; i++)
        #pragma unroll
        for (int j = 0; j < 8; j++)
            #pragma unroll
            for (int q = 0; q < 4; q++) acc[i][j][q] = 0.f;

    auto load_chunk = [&](int c) {
        const __half* Ap = (c < 32) ? A1 : A2;
        const __half* Bp = (c < 32) ? B1 : B2;
        const int k0 = (c & 31) * 32;          // halves
        const uint32_t st = sbase + (uint32_t)((c % NST) * STB);
        const __half* ga = Ap + (size_t)(m0 + tid) * DD + k0;
        const __half* gb = Bp + (size_t)(n0 + brow) * DD + k0 + bc0 * 8;
        #pragma unroll
        for (int q = 0; q < 4; q++)
            cp16(st + sw64(tid, q), ga + q * 8);
        #pragma unroll
        for (int q = 0; q < 2; q++)
            cp16(st + BOFF + sw64(brow, bc0 + q), gb + q * 8);
        cp_commit();
    };

    load_chunk(0);
    load_chunk(1);
    load_chunk(2);

    for (int c = 0; c < nch; c++) {
        if (c + 1 < nch) cp_wait<2>(); else cp_wait<0>();
        __syncthreads();
        if (c + 3 < nch) load_chunk(c + 3);

        const uint32_t Ab = sbase + (uint32_t)((c % NST) * STB);
        const uint32_t Bb = Ab + BOFF;
        #pragma unroll
        for (int ks = 0; ks < 2; ks++) {
            uint32_t a[4][4], bg[4][4];
            #pragma unroll
            for (int i = 0; i < 4; i++)
                ldm_x4(a[i], Ab + sw64(wm + i * 16 + a_rlo, 2 * ks + a_hb));
            #pragma unroll
            for (int g = 0; g < 4; g++)
                ldm_x4(bg[g], Bb + sw64(wn + g * 16 + b_rlo, 2 * ks + b_hb));
            #pragma unroll
            for (int i = 0; i < 4; i++)
                #pragma unroll
                for (int j = 0; j < 8; j++)
                    mma16(acc[i][j], a[i], &bg[j >> 1][(j & 1) * 2]);
        }
        // single barrier per chunk: next iteration's barrier orders compute
        // vs the load that overwrites this stage (4-stage ring, +3 == -1).
    }

    // epilogue
    float* Cf = (float*)Cv;
    __half* Ch = (__half*)Cv;
    float colsum[8][2];
    if (MODE == 4) {
        #pragma unroll
        for (int j = 0; j < 8; j++) { colsum[j][0] = 0.f; colsum[j][1] = 0.f; }
    }
    #pragma unroll
    for (int i = 0; i < 4; i++) {
        int grow = m0 + wm + i * 16 + r4;
        #pragma unroll
        for (int j = 0; j < 8; j++) {
            int gcol = n0 + wn + j * 8 + l4 * 2;
            float v0 = acc[i][j][0], v1 = acc[i][j][1];
            float v2 = acc[i][j][2], v3 = acc[i][j][3];
            if (MODE == 0 || MODE == 4) {
                *(float2*)(Cf + (size_t)grow * DD + gcol)       = make_float2(v0, v1);
                *(float2*)(Cf + (size_t)(grow + 8) * DD + gcol) = make_float2(v2, v3);
                if (MODE == 4) {
                    colsum[j][0] += v0 + v2;
                    colsum[j][1] += v1 + v3;
                }
            }
            if (MODE == 1) {
                *(uint32_t*)(Ch + (size_t)grow * DD + gcol)       = pack_h2(v0, v1);
                *(uint32_t*)(Ch + (size_t)(grow + 8) * DD + gcol) = pack_h2(v2, v3);
            }
            if (MODE == 2) {
                const float* vb0 = aux2 + (size_t)(grow >> 12) * DD + gcol;
                v0 = fmaxf(v0 + vb0[0], 0.f);
                v1 = fmaxf(v1 + vb0[1], 0.f);
                v2 = fmaxf(v2 + vb0[0], 0.f);
                v3 = fmaxf(v3 + vb0[1], 0.f);
                *(uint32_t*)(Ch + (size_t)grow * DD + gcol)       = pack_h2(v0, v1);
                *(uint32_t*)(Ch + (size_t)(grow + 8) * DD + gcol) = pack_h2(v2, v3);
            }
            if (MODE == 3) {
                const float* rp0 = aux1 + (size_t)grow * DD + gcol;
                const float* rp1 = aux1 + (size_t)(grow + 8) * DD + gcol;
                v0 += rp0[0] + aux2[gcol];
                v1 += rp0[1] + aux2[gcol + 1];
                v2 += rp1[0] + aux2[gcol];
                v3 += rp1[1] + aux2[gcol + 1];
                *(float2*)(Cf + (size_t)grow * DD + gcol)       = make_float2(v0, v1);
                *(float2*)(Cf + (size_t)(grow + 8) * DD + gcol) = make_float2(v2, v3);
            }
        }
    }

    if (MODE == 4) {
        // warp covers 64 rows, all within one 128-row segment
        // (wm<128 -> segment 2*by, else 2*by+1)
        #pragma unroll
        for (int j = 0; j < 8; j++) {
            #pragma unroll
            for (int q = 0; q < 2; q++) {
                float s = colsum[j][q];
                s += __shfl_xor_sync(0xffffffffu, s, 4);
                s += __shfl_xor_sync(0xffffffffu, s, 8);
                s += __shfl_xor_sync(0xffffffffu, s, 16);
                colsum[j][q] = s;
            }
        }
        float* red = (float*)sm;     // [4][128]
        __syncthreads();             // mainloop smem no longer in use
        if (lane < 4) {
            #pragma unroll
            for (int j = 0; j < 8; j++) {
                red[(wid & 3) * 128 + wn + j * 8 + lane * 2 + 0] = colsum[j][0];
                red[(wid & 3) * 128 + wn + j * 8 + lane * 2 + 1] = colsum[j][1];
            }
        }
        __syncthreads();
        {
            int half = tid >> 7;             // 0: rows 0-127, 1: rows 128-255
            int col = tid & 127;
            float s = red[half * 256 + col] + red[half * 256 + 128 + col];
            int b = m0 >> 12, seg = ((m0 >> 7) & (NSEG - 1)) + half;
            aux1[((size_t)b * NSEG + seg) * DD + n0 + col] = s;
        }
    }
}

// =================== transpose 1024x1024 fp32 -> half ====================
__global__ void k_transpose_h(const float* __restrict__ src, __half* __restrict__ dst) {
    __shared__ float t[32][33];
    int c0 = blockIdx.x * 32, r0 = blockIdx.y * 32;
    int x = threadIdx.x, y = threadIdx.y;
    #pragma unroll
    for (int j = 0; j < 32; j += 8)
        t[y + j][x] = src[(size_t)(r0 + y + j) * DD + c0 + x];
    __syncthreads();
    #pragma unroll
    for (int j = 0; j < 32; j += 8)
        dst[(size_t)(c0 + y + j) * DD + r0 + x] = __float2half_rn(t[x][y + j]);
}

// =================== fp32 -> half copy ===================================
__global__ void k_cvt_h(const float* __restrict__ src, __half* __restrict__ dst,
                        int n4) {
    int i = blockIdx.x * 256 + threadIdx.x;
    if (i < n4) {
        float4 v = ((const float4*)src)[i];
        ((uint2*)dst)[i] = make_uint2(pack_h2(v.x, v.y), pack_h2(v.z, v.w));
    }
}

// =================== vb = vector @ ff1_bot + b1 (half t1) ================
__global__ void k_vb(const float* __restrict__ vec, const __half* __restrict__ t1,
                     const float* __restrict__ bias, float* __restrict__ vb) {
    __shared__ float sv[DD];
    int b = blockIdx.y;
    for (int i = threadIdx.x; i < DD; i += 256) sv[i] = vec[(size_t)b * DD + i];
    __syncthreads();
    int d = blockIdx.x * 256 + threadIdx.x;
    const __half2* tp = (const __half2*)(t1 + (size_t)d * DD);
    float s = 0.f;
    #pragma unroll 4
    for (int i = 0; i < DD / 2; i++) {
        float2 a = __half22float2(tp[i]);
        s += a.x * sv[2 * i] + a.y * sv[2 * i + 1];
    }
    vb[(size_t)b * DD + d] = s + bias[d];
}

// ===== logits: warp-per-row, W^T in smem; also emits half copy of inputs ==
__global__ void k_logits(const float* __restrict__ inputs,
                         const float* __restrict__ W,
                         float* __restrict__ logits,
                         __half* __restrict__ inh) {
    extern __shared__ float Wt[];   // [16][1024]
    int tid = threadIdx.x;
    for (int idx = tid; idx < DD * HH; idx += 256) {
        int i = idx >> 4, h = idx & 15;
        Wt[h * DD + i] = W[idx];
    }
    __syncthreads();
    int warp = tid >> 5, lane = tid & 31;
    for (int rr = 0; rr < 4; rr++) {
        int r = blockIdx.x * 32 + warp * 4 + rr;
        const float4* xp = (const float4*)(inputs + (size_t)r * DD);
        uint2* hp = (uint2*)(inh + (size_t)r * DD);
        float acc[HH];
        #pragma unroll
        for (int h = 0; h < HH; h++) acc[h] = 0.f;
        #pragma unroll
        for (int j = 0; j < 8; j++) {
            float4 x = xp[lane + 32 * j];
            hp[lane + 32 * j] = make_uint2(pack_h2(x.x, x.y), pack_h2(x.z, x.w));
            int i0 = (lane + 32 * j) * 4;
            #pragma unroll
            for (int h = 0; h < HH; h++) {
                float4 w = *(const float4*)&Wt[h * DD + i0];
                acc[h] += x.x * w.x + x.y * w.y + x.z * w.z + x.w * w.w;
            }
        }
        #pragma unroll
        for (int h = 0; h < HH; h++) {
            #pragma unroll
            for (int o = 16; o > 0; o >>= 1)
                acc[h] += __shfl_xor_sync(0xffffffffu, acc[h], o);
        }
        if (lane == 0) {
            #pragma unroll
            for (int h = 0; h < HH; h++) logits[(size_t)r * HH + h] = acc[h];
        }
    }
}

// ------------- per (b,h): max over S, then att = exp((x-max)*temp) -------
__global__ void k_att_norm(float* __restrict__ logits, const float* __restrict__ temp) {
    int b = blockIdx.x >> 4, h = blockIdx.x & 15;
    float* p = logits + (size_t)b * SS * HH + h;
    float m = -3.4e38f;
    for (int s = threadIdx.x; s < SS; s += 256) m = fmaxf(m, p[(size_t)s * HH]);
    __shared__ float red[256];
    red[threadIdx.x] = m; __syncthreads();
    for (int o = 128; o > 0; o >>= 1) {
        if (threadIdx.x < o) red[threadIdx.x] = fmaxf(red[threadIdx.x], red[threadIdx.x + o]);
        __syncthreads();
    }
    m = red[0];
    float t = temp[h];
    for (int s = threadIdx.x; s < SS; s += 256) {
        size_t idx = (size_t)s * HH;
        p[idx] = expf((p[idx] - m) * t);
    }
}

// ---------------- scans (scan1 fused into v-GEMM) -----------------------
#define DD4 (DD/4)
__global__ void k_scan2(float4* __restrict__ segsum) {
    int b = blockIdx.x, c = threadIdx.x;
    float4 run = make_float4(0.f, 0.f, 0.f, 0.f);
    for (int seg = 0; seg < NSEG; seg++) {
        size_t idx = ((size_t)b * NSEG + seg) * DD4 + c;
        float4 v = segsum[idx];
        segsum[idx] = run;
        run.x += v.x; run.y += v.y; run.z += v.z; run.w += v.w;
    }
}

// prefix + att scaling; writes attn_out as half
__global__ void k_scan3(const float4* __restrict__ V, const float4* __restrict__ segsum,
                        const float* __restrict__ att, __half* __restrict__ out) {
    int c = blockIdx.x * 128 + threadIdx.x;
    int seg = blockIdx.y, b = blockIdx.z;
    int h = c >> 4;            // 16 float4 groups per head
    float4 run = segsum[((size_t)b * NSEG + seg) * DD4 + c];
    size_t base = (size_t)b * SS + (size_t)seg * SEG;
    const float4* p = V + base * DD4 + c;
    const float* ap = att + base * HH + h;
    __half* op = out + base * DD + c * 4;
    #pragma unroll 4
    for (int i = 0; i < SEG; i++) {
        float4 v = p[(size_t)i * DD4];
        run.x += v.x; run.y += v.y; run.z += v.z; run.w += v.w;
        float a = ap[(size_t)i * HH];
        float cnt = (float)(seg * SEG + i + 1);
        float s = a / (a * cnt + 1e-30f);
        *(uint32_t*)(op + (size_t)i * DD)     = pack_h2(run.x * s, run.y * s);
        *(uint32_t*)(op + (size_t)i * DD + 2) = pack_h2(run.z * s, run.w * s);
    }
}

// ---------------- LayerNorm (in place over d_out rows) ------------------
__global__ void k_ln(float* __restrict__ X, const float* __restrict__ g,
                     const float* __restrict__ be) {
    int r = blockIdx.x;
    float* p = X + (size_t)r * DD;
    int i = threadIdx.x * 4;
    float4 x = *(const float4*)(p + i);
    __shared__ float red[256];
    float s = x.x + x.y + x.z + x.w;
    red[threadIdx.x] = s; __syncthreads();
    for (int o = 128; o > 0; o >>= 1) {
        if (threadIdx.x < o) red[threadIdx.x] += red[threadIdx.x + o];
        __syncthreads();
    }
    float mean = red[0] * (1.f / DD);
    __syncthreads();
    float d0 = x.x - mean, d1 = x.y - mean, d2 = x.z - mean, d3 = x.w - mean;
    red[threadIdx.x] = d0 * d0 + d1 * d1 + d2 * d2 + d3 * d3;
    __syncthreads();
    for (int o = 128; o > 0; o >>= 1) {
        if (threadIdx.x < o) red[threadIdx.x] += red[threadIdx.x + o];
        __syncthreads();
    }
    float inv = rsqrtf(red[0] * (1.f / DD) + 1e-6f);
    float4 o4;
    o4.x = d0 * inv * g[i + 0] + be[i + 0];
    o4.y = d1 * inv * g[i + 1] + be[i + 1];
    o4.z = d2 * inv * g[i + 2] + be[i + 2];
    o4.w = d3 * inv * g[i + 3] + be[i + 3];
    *(float4*)(p + i) = o4;
}

// ---------------- launcher ----------------------------------------------
extern "C" void kernel_launch(void* const* d_in, const int* in_sizes, int n_in,
                              void* d_out, int out_size) {
    (void)in_sizes; (void)n_in; (void)out_size;
    const float* inputs   = (const float*)d_in[0];
    const float* vector   = (const float*)d_in[1];
    const float* attw     = (const float*)d_in[2];
    const float* temp     = (const float*)d_in[3];
    const float* values   = (const float*)d_in[4];
    const float* oper     = (const float*)d_in[5];
    const float* ff1      = (const float*)d_in[6];
    const float* ff1_bias = (const float*)d_in[7];
    const float* ff2      = (const float*)d_in[8];
    const float* ff2_bias = (const float*)d_in[9];
    const float* ln_gamma = (const float*)d_in[10];
    const float* ln_beta  = (const float*)d_in[11];
    float* out = (float*)d_out;

    float *att_p, *v_p, *seg_p, *vb_p;
    __half *inh_p, *attnh_p, *h1h_p, *valT_p, *f1tT_p, *t1_p, *ff2T_p, *operh_p, *owT_p;
    cudaGetSymbolAddress((void**)&att_p,   g_att);
    cudaGetSymbolAddress((void**)&v_p,     g_v);
    cudaGetSymbolAddress((void**)&seg_p,   g_seg);
    cudaGetSymbolAddress((void**)&vb_p,    g_vb);
    cudaGetSymbolAddress((void**)&inh_p,   g_in_h);
    cudaGetSymbolAddress((void**)&attnh_p, g_attn_h);
    cudaGetSymbolAddress((void**)&h1h_p,   g_h1h);
    cudaGetSymbolAddress((void**)&valT_p,  g_valTh);
    cudaGetSymbolAddress((void**)&f1tT_p,  g_f1tTh);
    cudaGetSymbolAddress((void**)&t1_p,    g_t1h);
    cudaGetSymbolAddress((void**)&ff2T_p,  g_ff2Th);
    cudaGetSymbolAddress((void**)&operh_p, g_operh);
    cudaGetSymbolAddress((void**)&owT_p,   g_owTh);

    cudaFuncSetAttribute(gemm_mma<1>, cudaFuncAttributeMaxDynamicSharedMemorySize, GEMM_SMEM);
    cudaFuncSetAttribute(gemm_mma<2>, cudaFuncAttributeMaxDynamicSharedMemorySize, GEMM_SMEM);
    cudaFuncSetAttribute(gemm_mma<3>, cudaFuncAttributeMaxDynamicSharedMemorySize, GEMM_SMEM);
    cudaFuncSetAttribute(gemm_mma<4>, cudaFuncAttributeMaxDynamicSharedMemorySize, GEMM_SMEM);
    cudaFuncSetAttribute(k_logits, cudaFuncAttributeMaxDynamicSharedMemorySize, 65536);

    dim3 tb(32, 8), tg(32, 32);
    // launches 1-5 (order chosen so launch #6 is the big v-GEMM for ncu)
    k_transpose_h<<<tg, tb>>>(values, valT_p);                 // 1
    k_logits<<<MR / 32, 256, 65536>>>(inputs, attw, att_p, inh_p); // 2
    k_transpose_h<<<tg, tb>>>(ff1, f1tT_p);                    // 3
    k_transpose_h<<<tg, tb>>>(ff1 + (size_t)DD * DD, t1_p);    // 4
    k_transpose_h<<<tg, tb>>>(ff2, ff2T_p);                    // 5

    // 6: v = inputs @ values (fp32 out) + fused segment sums
    gemm_mma<4><<<dim3(8, MR / 256), 256, GEMM_SMEM>>>(inh_p, valT_p, nullptr, nullptr,
                                                       v_p, seg_p, nullptr);

    k_cvt_h<<<(DD * DD / 4 + 255) / 256, 256>>>(oper, operh_p, DD * DD / 4);
    k_vb<<<dim3(DD / 256, BB), 256>>>(vector, t1_p, ff1_bias, vb_p);

    // owT[n][f] = sum_dv t1[n][dv] * operator[f][dv]  (half out)
    gemm_mma<1><<<dim3(8, 4), 256, GEMM_SMEM>>>(t1_p, operh_p, nullptr, nullptr,
                                                owT_p, nullptr, nullptr);

    k_att_norm<<<BB * HH, 256>>>(att_p, temp);

    // causal cumsum + att scaling -> half attn_out
    k_scan2<<<BB, 256>>>((float4*)seg_p);
    dim3 scanGrid(2, NSEG, BB);
    k_scan3<<<scanGrid, 128>>>((const float4*)v_p, (const float4*)seg_p, att_p, attnh_p);

    // h1 = relu(inputs@ff1_top + attn@OW + vb)  (half out)
    gemm_mma<2><<<dim3(8, MR / 256), 256, GEMM_SMEM>>>(inh_p, f1tT_p, attnh_p, owT_p,
                                                       h1h_p, nullptr, vb_p);

    // out = h1 @ ff2 + b2 + inputs (fp32)
    gemm_mma<3><<<dim3(8, MR / 256), 256, GEMM_SMEM>>>(h1h_p, ff2T_p, nullptr, nullptr,
                                                       out, (float*)inputs, ff2_bias);

    k_ln<<<MR, 256>>>(out, ln_gamma, ln_beta);
}

// round 13
// speedup vs baseline: 1.3628x; 1.3628x over previous
#include <cuda_runtime.h>
#include <cuda_fp16.h>
#include <math.h>
#include <stdint.h>

// Problem constants
#define BB   4
#define SS   4096
#define DD   1024
#define HH   16
#define MR   (BB*SS)          // 16384 rows
#define SEG  128
#define NSEG (SS/SEG)         // 32

#define NST  3                // pipeline stages
#define STB  32768            // bytes per stage (A 16KB + B 16KB)
#define GEMM_SMEM (NST*STB)   // 96 KB

// ---------------- scratch (static device globals) ------------------------
__device__ float  g_att[(size_t)BB*SS*HH];
__device__ float  g_v[(size_t)MR*DD];          // v (fp32, pre-scan)
__device__ float  g_seg[(size_t)BB*NSEG*DD];
__device__ float  g_vb [(size_t)BB*DD];
__device__ __half g_in_h[(size_t)MR*DD];       // inputs (half)
__device__ __half g_attn_h[(size_t)MR*DD];     // attn_out (half)
__device__ __half g_h1h[(size_t)MR*DD];        // ff1 hidden (half)
__device__ __half g_valTh[(size_t)DD*DD];
__device__ __half g_f1tTh[(size_t)DD*DD];
__device__ __half g_t1h [(size_t)DD*DD];
__device__ __half g_ff2Th[(size_t)DD*DD];
__device__ __half g_operh[(size_t)DD*DD];
__device__ __half g_owTh[(size_t)DD*DD];

// =================== helpers =============================================
__device__ __forceinline__ uint32_t smem_u32(const void* p) {
    uint32_t a;
    asm("{ .reg .u64 t; cvta.to.shared.u64 t, %1; cvt.u32.u64 %0, t; }"
        : "=r"(a) : "l"(p));
    return a;
}
__device__ __forceinline__ void cp16(uint32_t s, const void* g) {
    asm volatile("cp.async.cg.shared.global [%0], [%1], 16;"
                 :: "r"(s), "l"(g) : "memory");
}
__device__ __forceinline__ void cp_commit() {
    asm volatile("cp.async.commit_group;" ::: "memory");
}
template<int N>
__device__ __forceinline__ void cp_wait() {
    asm volatile("cp.async.wait_group %0;" :: "n"(N) : "memory");
}
__device__ __forceinline__ void ldm_x4(uint32_t* r, uint32_t addr) {
    asm volatile("ldmatrix.sync.aligned.m8n8.x4.shared.b16 {%0,%1,%2,%3}, [%4];"
                 : "=r"(r[0]), "=r"(r[1]), "=r"(r[2]), "=r"(r[3]) : "r"(addr));
}
__device__ __forceinline__ void mma16(float* d, const uint32_t* a, const uint32_t* b) {
    asm volatile(
        "mma.sync.aligned.m16n8k16.row.col.f32.f16.f16.f32 "
        "{%0,%1,%2,%3}, {%4,%5,%6,%7}, {%8,%9}, {%0,%1,%2,%3};"
        : "+f"(d[0]), "+f"(d[1]), "+f"(d[2]), "+f"(d[3])
        : "r"(a[0]), "r"(a[1]), "r"(a[2]), "r"(a[3]), "r"(b[0]), "r"(b[1]));
}
__device__ __forceinline__ uint32_t pack_h2(float a, float b) {
    __half2 h = __floats2half2_rn(a, b);
    return *reinterpret_cast<uint32_t*>(&h);
}

// =================== fp16 mma.sync GEMM (ldmatrix + 3-stage) =============
// C[m,n] = sum_k A1[m,k]*B1[n,k] (+ A2[m,k]*B2[n,k] if A2), K=1024 per pair.
// MODE 0: fp32 out              MODE 1: half out
// MODE 2: half(relu(acc + aux2[(row>>12)*DD+col]))
// MODE 3: fp32: acc + aux1[row*DD+col] + aux2[col]
// MODE 4: fp32 out + per-tile column sums -> aux1 (segsum; tile == segment)
template<int MODE>
__global__ void __launch_bounds__(256, 2)
gemm_mma(const __half* __restrict__ A1, const __half* __restrict__ B1,
         const __half* __restrict__ A2, const __half* __restrict__ B2,
         void* __restrict__ Cv,
         float* __restrict__ aux1, const float* __restrict__ aux2) {
    extern __shared__ char sm[];
    const uint32_t sbase = smem_u32(sm);
    const int tid = threadIdx.x, lane = tid & 31, wid = tid >> 5;
    const int wm = (wid & 3) * 32, wn = (wid >> 2) * 64;
    const int m0 = blockIdx.y * 128, n0 = blockIdx.x * 128;
    const int r4 = lane >> 2, l4 = lane & 3;
    const int nch = A2 ? 32 : 16;   // chunks of K=64 halves

    // cp.async mapping: row = tid>>1, 4 x 16B chunks at (tid&1)*4
    const int lrow = tid >> 1;
    const int lc0  = (tid & 1) * 4;
    const int lr7  = lrow & 7;

    // ldmatrix per-lane row/parity
    const int a_row = wm + (lane & 15);
    const int a_hb  = lane >> 4;
    const int b_rlo = (lane & 7) + ((lane >> 4) & 1) * 8;
    const int b_hb  = (lane >> 3) & 1;

    float acc[2][8][4];
    #pragma unroll
    for (int i = 0; i < 2; i++)
        #pragma unroll
        for (int j = 0; j < 8; j++)
            #pragma unroll
            for (int q = 0; q < 4; q++) acc[i][j][q] = 0.f;

    auto load_chunk = [&](int c) {
        const __half* Ap = (c < 16) ? A1 : A2;
        const __half* Bp = (c < 16) ? B1 : B2;
        const int k0 = (c & 15) * 64;          // halves
        const uint32_t st = sbase + (uint32_t)((c % NST) * STB);
        const __half* ga = Ap + (size_t)(m0 + lrow) * DD + k0 + lc0 * 8;
        const __half* gb = Bp + (size_t)(n0 + lrow) * DD + k0 + lc0 * 8;
        const uint32_t rowoff = (uint32_t)lrow * 128u;
        #pragma unroll
        for (int q = 0; q < 4; q++) {
            uint32_t sc = (uint32_t)(((lc0 + q) ^ lr7) << 4);
            cp16(st + rowoff + sc,           ga + q * 8);
            cp16(st + 16384u + rowoff + sc,  gb + q * 8);
        }
        cp_commit();
    };

    load_chunk(0);
    load_chunk(1);

    for (int c = 0; c < nch; c++) {
        if (c + 1 < nch) cp_wait<1>(); else cp_wait<0>();
        __syncthreads();
        if (c + 2 < nch) load_chunk(c + 2);   // overlap load issue with compute

        const uint32_t Ab = sbase + (uint32_t)((c % NST) * STB);
        const uint32_t Bb = Ab + 16384u;

        // B-fragment double buffer: prefetch ks+1 while computing ks
        uint32_t bgbuf[2][4][4];
        #pragma unroll
        for (int g = 0; g < 4; g++) {
            int row = wn + g * 16 + b_rlo;
            ldm_x4(bgbuf[0][g], Bb + row * 128 + ((b_hb ^ (row & 7)) << 4));
        }
        #pragma unroll
        for (int ks = 0; ks < 4; ks++) {     // k16 steps within K=64 chunk
            uint32_t a[2][4];
            #pragma unroll
            for (int i = 0; i < 2; i++) {
                int row = a_row + i * 16;
                int ch = 2 * ks + a_hb;
                ldm_x4(a[i], Ab + row * 128 + ((ch ^ (row & 7)) << 4));
            }
            if (ks < 3) {
                #pragma unroll
                for (int g = 0; g < 4; g++) {
                    int row = wn + g * 16 + b_rlo;
                    int ch = 2 * (ks + 1) + b_hb;
                    ldm_x4(bgbuf[(ks + 1) & 1][g],
                           Bb + row * 128 + ((ch ^ (row & 7)) << 4));
                }
            }
            #pragma unroll
            for (int i = 0; i < 2; i++)
                #pragma unroll
                for (int j = 0; j < 8; j++)
                    mma16(acc[i][j], a[i], &bgbuf[ks & 1][j >> 1][(j & 1) * 2]);
        }
        // single barrier per chunk: next iteration's barrier orders compute
        // vs the load that overwrites this stage (3-stage ring, +2 == -1).
    }

    // epilogue
    float* Cf = (float*)Cv;
    __half* Ch = (__half*)Cv;
    float colsum[8][2];
    if (MODE == 4) {
        #pragma unroll
        for (int j = 0; j < 8; j++) { colsum[j][0] = 0.f; colsum[j][1] = 0.f; }
    }
    #pragma unroll
    for (int i = 0; i < 2; i++) {
        int grow = m0 + wm + i * 16 + r4;
        #pragma unroll
        for (int j = 0; j < 8; j++) {
            int gcol = n0 + wn + j * 8 + l4 * 2;
            float v0 = acc[i][j][0], v1 = acc[i][j][1];
            float v2 = acc[i][j][2], v3 = acc[i][j][3];
            if (MODE == 0 || MODE == 4) {
                *(float2*)(Cf + (size_t)grow * DD + gcol)       = make_float2(v0, v1);
                *(float2*)(Cf + (size_t)(grow + 8) * DD + gcol) = make_float2(v2, v3);
                if (MODE == 4) {
                    colsum[j][0] += v0 + v2;
                    colsum[j][1] += v1 + v3;
                }
            }
            if (MODE == 1) {
                *(uint32_t*)(Ch + (size_t)grow * DD + gcol)       = pack_h2(v0, v1);
                *(uint32_t*)(Ch + (size_t)(grow + 8) * DD + gcol) = pack_h2(v2, v3);
            }
            if (MODE == 2) {
                const float* vb0 = aux2 + (size_t)(grow >> 12) * DD + gcol;
                v0 = fmaxf(v0 + vb0[0], 0.f);
                v1 = fmaxf(v1 + vb0[1], 0.f);
                v2 = fmaxf(v2 + vb0[0], 0.f);
                v3 = fmaxf(v3 + vb0[1], 0.f);
                *(uint32_t*)(Ch + (size_t)grow * DD + gcol)       = pack_h2(v0, v1);
                *(uint32_t*)(Ch + (size_t)(grow + 8) * DD + gcol) = pack_h2(v2, v3);
            }
            if (MODE == 3) {
                const float* rp0 = aux1 + (size_t)grow * DD + gcol;
                const float* rp1 = aux1 + (size_t)(grow + 8) * DD + gcol;
                v0 += rp0[0] + aux2[gcol];
                v1 += rp0[1] + aux2[gcol + 1];
                v2 += rp1[0] + aux2[gcol];
                v3 += rp1[1] + aux2[gcol + 1];
                *(float2*)(Cf + (size_t)grow * DD + gcol)       = make_float2(v0, v1);
                *(float2*)(Cf + (size_t)(grow + 8) * DD + gcol) = make_float2(v2, v3);
            }
        }
    }

    if (MODE == 4) {
        // reduce over r4 (lane bits 2..4) -> every lane holds sum for its l4
        #pragma unroll
        for (int j = 0; j < 8; j++) {
            #pragma unroll
            for (int q = 0; q < 2; q++) {
                float s = colsum[j][q];
                s += __shfl_xor_sync(0xffffffffu, s, 4);
                s += __shfl_xor_sync(0xffffffffu, s, 8);
                s += __shfl_xor_sync(0xffffffffu, s, 16);
                colsum[j][q] = s;
            }
        }
        float* red = (float*)sm;     // [4][128]
        __syncthreads();             // mainloop smem no longer in use
        if (lane < 4) {
            #pragma unroll
            for (int j = 0; j < 8; j++) {
                red[(wid & 3) * 128 + wn + j * 8 + lane * 2 + 0] = colsum[j][0];
                red[(wid & 3) * 128 + wn + j * 8 + lane * 2 + 1] = colsum[j][1];
            }
        }
        __syncthreads();
        if (tid < 128) {
            float s = red[tid] + red[128 + tid] + red[256 + tid] + red[384 + tid];
            int b = m0 >> 12, seg = (m0 >> 7) & (NSEG - 1);
            aux1[((size_t)b * NSEG + seg) * DD + n0 + tid] = s;
        }
    }
}

// =================== transpose 1024x1024 fp32 -> half ====================
__global__ void k_transpose_h(const float* __restrict__ src, __half* __restrict__ dst) {
    __shared__ float t[32][33];
    int c0 = blockIdx.x * 32, r0 = blockIdx.y * 32;
    int x = threadIdx.x, y = threadIdx.y;
    #pragma unroll
    for (int j = 0; j < 32; j += 8)
        t[y + j][x] = src[(size_t)(r0 + y + j) * DD + c0 + x];
    __syncthreads();
    #pragma unroll
    for (int j = 0; j < 32; j += 8)
        dst[(size_t)(c0 + y + j) * DD + r0 + x] = __float2half_rn(t[x][y + j]);
}

// =================== fp32 -> half copy ===================================
__global__ void k_cvt_h(const float* __restrict__ src, __half* __restrict__ dst,
                        int n4) {
    int i = blockIdx.x * 256 + threadIdx.x;
    if (i < n4) {
        float4 v = ((const float4*)src)[i];
        ((uint2*)dst)[i] = make_uint2(pack_h2(v.x, v.y), pack_h2(v.z, v.w));
    }
}

// =================== vb = vector @ ff1_bot + b1 (half t1) ================
__global__ void k_vb(const float* __restrict__ vec, const __half* __restrict__ t1,
                     const float* __restrict__ bias, float* __restrict__ vb) {
    __shared__ float sv[DD];
    int b = blockIdx.y;
    for (int i = threadIdx.x; i < DD; i += 256) sv[i] = vec[(size_t)b * DD + i];
    __syncthreads();
    int d = blockIdx.x * 256 + threadIdx.x;
    const __half2* tp = (const __half2*)(t1 + (size_t)d * DD);
    float s = 0.f;
    #pragma unroll 4
    for (int i = 0; i < DD / 2; i++) {
        float2 a = __half22float2(tp[i]);
        s += a.x * sv[2 * i] + a.y * sv[2 * i + 1];
    }
    vb[(size_t)b * DD + d] = s + bias[d];
}

// ===== logits: warp-per-row, W^T in smem; also emits half copy of inputs ==
__global__ void k_logits(const float* __restrict__ inputs,
                         const float* __restrict__ W,
                         float* __restrict__ logits,
                         __half* __restrict__ inh) {
    extern __shared__ float Wt[];   // [16][1024]
    int tid = threadIdx.x;
    for (int idx = tid; idx < DD * HH; idx += 256) {
        int i = idx >> 4, h = idx & 15;
        Wt[h * DD + i] = W[idx];
    }
    __syncthreads();
    int warp = tid >> 5, lane = tid & 31;
    for (int rr = 0; rr < 4; rr++) {
        int r = blockIdx.x * 32 + warp * 4 + rr;
        const float4* xp = (const float4*)(inputs + (size_t)r * DD);
        uint2* hp = (uint2*)(inh + (size_t)r * DD);
        float acc[HH];
        #pragma unroll
        for (int h = 0; h < HH; h++) acc[h] = 0.f;
        #pragma unroll
        for (int j = 0; j < 8; j++) {
            float4 x = xp[lane + 32 * j];
            hp[lane + 32 * j] = make_uint2(pack_h2(x.x, x.y), pack_h2(x.z, x.w));
            int i0 = (lane + 32 * j) * 4;
            #pragma unroll
            for (int h = 0; h < HH; h++) {
                float4 w = *(const float4*)&Wt[h * DD + i0];
                acc[h] += x.x * w.x + x.y * w.y + x.z * w.z + x.w * w.w;
            }
        }
        #pragma unroll
        for (int h = 0; h < HH; h++) {
            #pragma unroll
            for (int o = 16; o > 0; o >>= 1)
                acc[h] += __shfl_xor_sync(0xffffffffu, acc[h], o);
        }
        if (lane == 0) {
            #pragma unroll
            for (int h = 0; h < HH; h++) logits[(size_t)r * HH + h] = acc[h];
        }
    }
}

// ------------- per (b,h): max over S, then att = exp((x-max)*temp) -------
__global__ void k_att_norm(float* __restrict__ logits, const float* __restrict__ temp) {
    int b = blockIdx.x >> 4, h = blockIdx.x & 15;
    float* p = logits + (size_t)b * SS * HH + h;
    float m = -3.4e38f;
    for (int s = threadIdx.x; s < SS; s += 256) m = fmaxf(m, p[(size_t)s * HH]);
    __shared__ float red[256];
    red[threadIdx.x] = m; __syncthreads();
    for (int o = 128; o > 0; o >>= 1) {
        if (threadIdx.x < o) red[threadIdx.x] = fmaxf(red[threadIdx.x], red[threadIdx.x + o]);
        __syncthreads();
    }
    m = red[0];
    float t = temp[h];
    for (int s = threadIdx.x; s < SS; s += 256) {
        size_t idx = (size_t)s * HH;
        p[idx] = expf((p[idx] - m) * t);
    }
}

// ---------------- scans (scan1 fused into v-GEMM) -----------------------
#define DD4 (DD/4)
__global__ void k_scan2(float4* __restrict__ segsum) {
    int b = blockIdx.x, c = threadIdx.x;
    float4 run = make_float4(0.f, 0.f, 0.f, 0.f);
    for (int seg = 0; seg < NSEG; seg++) {
        size_t idx = ((size_t)b * NSEG + seg) * DD4 + c;
        float4 v = segsum[idx];
        segsum[idx] = run;
        run.x += v.x; run.y += v.y; run.z += v.z; run.w += v.w;
    }
}

// prefix + att scaling; writes attn_out as half
__global__ void k_scan3(const float4* __restrict__ V, const float4* __restrict__ segsum,
                        const float* __restrict__ att, __half* __restrict__ out) {
    int c = blockIdx.x * 128 + threadIdx.x;
    int seg = blockIdx.y, b = blockIdx.z;
    int h = c >> 4;            // 16 float4 groups per head
    float4 run = segsum[((size_t)b * NSEG + seg) * DD4 + c];
    size_t base = (size_t)b * SS + (size_t)seg * SEG;
    const float4* p = V + base * DD4 + c;
    const float* ap = att + base * HH + h;
    __half* op = out + base * DD + c * 4;
    #pragma unroll 4
    for (int i = 0; i < SEG; i++) {
        float4 v = p[(size_t)i * DD4];
        run.x += v.x; run.y += v.y; run.z += v.z; run.w += v.w;
        float a = ap[(size_t)i * HH];
        float cnt = (float)(seg * SEG + i + 1);
        float s = __fdividef(a, a * cnt + 1e-30f);
        *(uint32_t*)(op + (size_t)i * DD)     = pack_h2(run.x * s, run.y * s);
        *(uint32_t*)(op + (size_t)i * DD + 2) = pack_h2(run.z * s, run.w * s);
    }
}

// ---------------- LayerNorm (in place over d_out rows) ------------------
__global__ void k_ln(float* __restrict__ X, const float* __restrict__ g,
                     const float* __restrict__ be) {
    int r = blockIdx.x;
    float* p = X + (size_t)r * DD;
    int i = threadIdx.x * 4;
    float4 x = *(const float4*)(p + i);
    __shared__ float red[256];
    float s = x.x + x.y + x.z + x.w;
    red[threadIdx.x] = s; __syncthreads();
    for (int o = 128; o > 0; o >>= 1) {
        if (threadIdx.x < o) red[threadIdx.x] += red[threadIdx.x + o];
        __syncthreads();
    }
    float mean = red[0] * (1.f / DD);
    __syncthreads();
    float d0 = x.x - mean, d1 = x.y - mean, d2 = x.z - mean, d3 = x.w - mean;
    red[threadIdx.x] = d0 * d0 + d1 * d1 + d2 * d2 + d3 * d3;
    __syncthreads();
    for (int o = 128; o > 0; o >>= 1) {
        if (threadIdx.x < o) red[threadIdx.x] += red[threadIdx.x + o];
        __syncthreads();
    }
    float inv = rsqrtf(red[0] * (1.f / DD) + 1e-6f);
    float4 o4;
    o4.x = d0 * inv * g[i + 0] + be[i + 0];
    o4.y = d1 * inv * g[i + 1] + be[i + 1];
    o4.z = d2 * inv * g[i + 2] + be[i + 2];
    o4.w = d3 * inv * g[i + 3] + be[i + 3];
    *(float4*)(p + i) = o4;
}

// ---------------- launcher ----------------------------------------------
extern "C" void kernel_launch(void* const* d_in, const int* in_sizes, int n_in,
                              void* d_out, int out_size) {
    (void)in_sizes; (void)n_in; (void)out_size;
    const float* inputs   = (const float*)d_in[0];
    const float* vector   = (const float*)d_in[1];
    const float* attw     = (const float*)d_in[2];
    const float* temp     = (const float*)d_in[3];
    const float* values   = (const float*)d_in[4];
    const float* oper     = (const float*)d_in[5];
    const float* ff1      = (const float*)d_in[6];
    const float* ff1_bias = (const float*)d_in[7];
    const float* ff2      = (const float*)d_in[8];
    const float* ff2_bias = (const float*)d_in[9];
    const float* ln_gamma = (const float*)d_in[10];
    const float* ln_beta  = (const float*)d_in[11];
    float* out = (float*)d_out;

    float *att_p, *v_p, *seg_p, *vb_p;
    __half *inh_p, *attnh_p, *h1h_p, *valT_p, *f1tT_p, *t1_p, *ff2T_p, *operh_p, *owT_p;
    cudaGetSymbolAddress((void**)&att_p,   g_att);
    cudaGetSymbolAddress((void**)&v_p,     g_v);
    cudaGetSymbolAddress((void**)&seg_p,   g_seg);
    cudaGetSymbolAddress((void**)&vb_p,    g_vb);
    cudaGetSymbolAddress((void**)&inh_p,   g_in_h);
    cudaGetSymbolAddress((void**)&attnh_p, g_attn_h);
    cudaGetSymbolAddress((void**)&h1h_p,   g_h1h);
    cudaGetSymbolAddress((void**)&valT_p,  g_valTh);
    cudaGetSymbolAddress((void**)&f1tT_p,  g_f1tTh);
    cudaGetSymbolAddress((void**)&t1_p,    g_t1h);
    cudaGetSymbolAddress((void**)&ff2T_p,  g_ff2Th);
    cudaGetSymbolAddress((void**)&operh_p, g_operh);
    cudaGetSymbolAddress((void**)&owT_p,   g_owTh);

    cudaFuncSetAttribute(gemm_mma<1>, cudaFuncAttributeMaxDynamicSharedMemorySize, GEMM_SMEM);
    cudaFuncSetAttribute(gemm_mma<2>, cudaFuncAttributeMaxDynamicSharedMemorySize, GEMM_SMEM);
    cudaFuncSetAttribute(gemm_mma<3>, cudaFuncAttributeMaxDynamicSharedMemorySize, GEMM_SMEM);
    cudaFuncSetAttribute(gemm_mma<4>, cudaFuncAttributeMaxDynamicSharedMemorySize, GEMM_SMEM);
    cudaFuncSetAttribute(k_logits, cudaFuncAttributeMaxDynamicSharedMemorySize, 65536);

    dim3 tb(32, 8), tg(32, 32);
    // launches 1-5 (order chosen so launch #6 is the big v-GEMM for ncu)
    k_transpose_h<<<tg, tb>>>(values, valT_p);                      // 1
    k_logits<<<MR / 32, 256, 65536>>>(inputs, attw, att_p, inh_p);  // 2
    k_transpose_h<<<tg, tb>>>(ff1, f1tT_p);                         // 3
    k_transpose_h<<<tg, tb>>>(ff1 + (size_t)DD * DD, t1_p);         // 4
    k_transpose_h<<<tg, tb>>>(ff2, ff2T_p);                         // 5

    // 6: v = inputs @ values (fp32 out) + fused segment sums
    gemm_mma<4><<<dim3(8, MR / 128), 256, GEMM_SMEM>>>(inh_p, valT_p, nullptr, nullptr,
                                                       v_p, seg_p, nullptr);

    k_cvt_h<<<(DD * DD / 4 + 255) / 256, 256>>>(oper, operh_p, DD * DD / 4);
    k_vb<<<dim3(DD / 256, BB), 256>>>(vector, t1_p, ff1_bias, vb_p);

    // owT[n][f] = sum_dv t1[n][dv] * operator[f][dv]  (half out)
    gemm_mma<1><<<dim3(8, 8), 256, GEMM_SMEM>>>(t1_p, operh_p, nullptr, nullptr,
                                                owT_p, nullptr, nullptr);

    k_att_norm<<<BB * HH, 256>>>(att_p, temp);

    // causal cumsum + att scaling -> half attn_out
    k_scan2<<<BB, 256>>>((float4*)seg_p);
    dim3 scanGrid(2, NSEG, BB);
    k_scan3<<<scanGrid, 128>>>((const float4*)v_p, (const float4*)seg_p, att_p, attnh_p);

    // h1 = relu(inputs@ff1_top + attn@OW + vb)  (half out)
    gemm_mma<2><<<dim3(8, MR / 128), 256, GEMM_SMEM>>>(inh_p, f1tT_p, attnh_p, owT_p,
                                                       h1h_p, nullptr, vb_p);

    // out = h1 @ ff2 + b2 + inputs (fp32)
    gemm_mma<3><<<dim3(8, MR / 128), 256, GEMM_SMEM>>>(h1h_p, ff2T_p, nullptr, nullptr,
                                                       out, (float*)inputs, ff2_bias);

    k_ln<<<MR, 256>>>(out, ln_gamma, ln_beta);
}

// round 15
// speedup vs baseline: 1.4289x; 1.0485x over previous
#include <cuda_runtime.h>
#include <cuda_fp16.h>
#include <math.h>
#include <stdint.h>

// Problem constants
#define BB   4
#define SS   4096
#define DD   1024
#define HH   16
#define MR   (BB*SS)          // 16384 rows
#define SEG  128
#define NSEG (SS/SEG)         // 32

#define NST  3                // pipeline stages
#define STB  32768            // bytes per stage (A 16KB + B 16KB)
#define GEMM_SMEM (NST*STB)   // 96 KB

// ---------------- scratch (static device globals) ------------------------
__device__ float  g_logit[(size_t)BB*SS*HH];   // raw logits
__device__ int    g_maxi[BB*HH];               // encoded per-(b,h) max
__device__ float  g_v[(size_t)MR*DD];          // v (fp32, pre-scan)
__device__ float  g_seg[(size_t)BB*NSEG*DD];
__device__ float  g_vb [(size_t)BB*DD];
__device__ __half g_in_h[(size_t)MR*DD];       // inputs (half)
__device__ __half g_attn_h[(size_t)MR*DD];     // attn_out (half)
__device__ __half g_h1h[(size_t)MR*DD];        // ff1 hidden (half)
__device__ __half g_valTh[(size_t)DD*DD];
__device__ __half g_f1tTh[(size_t)DD*DD];
__device__ __half g_t1h [(size_t)DD*DD];
__device__ __half g_ff2Th[(size_t)DD*DD];
__device__ __half g_operh[(size_t)DD*DD];
__device__ __half g_owTh[(size_t)DD*DD];

// =================== helpers =============================================
__device__ __forceinline__ uint32_t smem_u32(const void* p) {
    uint32_t a;
    asm("{ .reg .u64 t; cvta.to.shared.u64 t, %1; cvt.u32.u64 %0, t; }"
        : "=r"(a) : "l"(p));
    return a;
}
__device__ __forceinline__ void cp16(uint32_t s, const void* g) {
    asm volatile("cp.async.cg.shared.global [%0], [%1], 16;"
                 :: "r"(s), "l"(g) : "memory");
}
__device__ __forceinline__ void cp_commit() {
    asm volatile("cp.async.commit_group;" ::: "memory");
}
template<int N>
__device__ __forceinline__ void cp_wait() {
    asm volatile("cp.async.wait_group %0;" :: "n"(N) : "memory");
}
__device__ __forceinline__ void ldm_x4(uint32_t* r, uint32_t addr) {
    asm volatile("ldmatrix.sync.aligned.m8n8.x4.shared.b16 {%0,%1,%2,%3}, [%4];"
                 : "=r"(r[0]), "=r"(r[1]), "=r"(r[2]), "=r"(r[3]) : "r"(addr));
}
__device__ __forceinline__ void mma16(float* d, const uint32_t* a, const uint32_t* b) {
    asm volatile(
        "mma.sync.aligned.m16n8k16.row.col.f32.f16.f16.f32 "
        "{%0,%1,%2,%3}, {%4,%5,%6,%7}, {%8,%9}, {%0,%1,%2,%3};"
        : "+f"(d[0]), "+f"(d[1]), "+f"(d[2]), "+f"(d[3])
        : "r"(a[0]), "r"(a[1]), "r"(a[2]), "r"(a[3]), "r"(b[0]), "r"(b[1]));
}
__device__ __forceinline__ uint32_t pack_h2(float a, float b) {
    __half2 h = __floats2half2_rn(a, b);
    return *reinterpret_cast<uint32_t*>(&h);
}
// order-preserving float<->int encoding for atomicMax over floats
__device__ __forceinline__ int enc_f(float f) {
    int e = __float_as_int(f);
    return e >= 0 ? e : (e ^ 0x7FFFFFFF);
}
__device__ __forceinline__ float dec_f(int e) {
    return __int_as_float(e >= 0 ? e : (e ^ 0x7FFFFFFF));
}

// =================== fp16 mma.sync GEMM (ldmatrix + 3-stage) =============
// C[m,n] = sum_k A1[m,k]*B1[n,k] (+ A2[m,k]*B2[n,k] if A2), K=1024 per pair.
// MODE 0: fp32 out              MODE 1: half out
// MODE 2: half(relu(acc + aux2[(row>>12)*DD+col]))
// MODE 3: fp32: acc + aux1[row*DD+col] + aux2[col]
// MODE 4: fp32 out + per-tile column sums -> aux1 (segsum; tile == segment)
template<int MODE>
__global__ void __launch_bounds__(256, 2)
gemm_mma(const __half* __restrict__ A1, const __half* __restrict__ B1,
         const __half* __restrict__ A2, const __half* __restrict__ B2,
         void* __restrict__ Cv,
         float* __restrict__ aux1, const float* __restrict__ aux2) {
    extern __shared__ char sm[];
    const uint32_t sbase = smem_u32(sm);
    const int tid = threadIdx.x, lane = tid & 31, wid = tid >> 5;
    const int wm = (wid & 3) * 32, wn = (wid >> 2) * 64;
    const int m0 = blockIdx.y * 128, n0 = blockIdx.x * 128;
    const int r4 = lane >> 2, l4 = lane & 3;
    const int nch = A2 ? 32 : 16;   // chunks of K=64 halves

    const int lrow = tid >> 1;
    const int lc0  = (tid & 1) * 4;
    const int lr7  = lrow & 7;

    const int a_row = wm + (lane & 15);
    const int a_hb  = lane >> 4;
    const int b_rlo = (lane & 7) + ((lane >> 4) & 1) * 8;
    const int b_hb  = (lane >> 3) & 1;

    float acc[2][8][4];
    #pragma unroll
    for (int i = 0; i < 2; i++)
        #pragma unroll
        for (int j = 0; j < 8; j++)
            #pragma unroll
            for (int q = 0; q < 4; q++) acc[i][j][q] = 0.f;

    auto load_chunk = [&](int c) {
        const __half* Ap = (c < 16) ? A1 : A2;
        const __half* Bp = (c < 16) ? B1 : B2;
        const int k0 = (c & 15) * 64;
        const uint32_t st = sbase + (uint32_t)((c % NST) * STB);
        const __half* ga = Ap + (size_t)(m0 + lrow) * DD + k0 + lc0 * 8;
        const __half* gb = Bp + (size_t)(n0 + lrow) * DD + k0 + lc0 * 8;
        const uint32_t rowoff = (uint32_t)lrow * 128u;
        #pragma unroll
        for (int q = 0; q < 4; q++) {
            uint32_t sc = (uint32_t)(((lc0 + q) ^ lr7) << 4);
            cp16(st + rowoff + sc,           ga + q * 8);
            cp16(st + 16384u + rowoff + sc,  gb + q * 8);
        }
        cp_commit();
    };

    load_chunk(0);
    load_chunk(1);

    for (int c = 0; c < nch; c++) {
        if (c + 1 < nch) cp_wait<1>(); else cp_wait<0>();
        __syncthreads();
        if (c + 2 < nch) load_chunk(c + 2);

        const uint32_t Ab = sbase + (uint32_t)((c % NST) * STB);
        const uint32_t Bb = Ab + 16384u;

        uint32_t bgbuf[2][4][4];
        #pragma unroll
        for (int g = 0; g < 4; g++) {
            int row = wn + g * 16 + b_rlo;
            ldm_x4(bgbuf[0][g], Bb + row * 128 + ((b_hb ^ (row & 7)) << 4));
        }
        #pragma unroll
        for (int ks = 0; ks < 4; ks++) {
            uint32_t a[2][4];
            #pragma unroll
            for (int i = 0; i < 2; i++) {
                int row = a_row + i * 16;
                int ch = 2 * ks + a_hb;
                ldm_x4(a[i], Ab + row * 128 + ((ch ^ (row & 7)) << 4));
            }
            if (ks < 3) {
                #pragma unroll
                for (int g = 0; g < 4; g++) {
                    int row = wn + g * 16 + b_rlo;
                    int ch = 2 * (ks + 1) + b_hb;
                    ldm_x4(bgbuf[(ks + 1) & 1][g],
                           Bb + row * 128 + ((ch ^ (row & 7)) << 4));
                }
            }
            #pragma unroll
            for (int i = 0; i < 2; i++)
                #pragma unroll
                for (int j = 0; j < 8; j++)
                    mma16(acc[i][j], a[i], &bgbuf[ks & 1][j >> 1][(j & 1) * 2]);
        }
    }

    // epilogue
    float* Cf = (float*)Cv;
    __half* Ch = (__half*)Cv;
    float colsum[8][2];
    if (MODE == 4) {
        #pragma unroll
        for (int j = 0; j < 8; j++) { colsum[j][0] = 0.f; colsum[j][1] = 0.f; }
    }
    #pragma unroll
    for (int i = 0; i < 2; i++) {
        int grow = m0 + wm + i * 16 + r4;
        #pragma unroll
        for (int j = 0; j < 8; j++) {
            int gcol = n0 + wn + j * 8 + l4 * 2;
            float v0 = acc[i][j][0], v1 = acc[i][j][1];
            float v2 = acc[i][j][2], v3 = acc[i][j][3];
            if (MODE == 0 || MODE == 4) {
                *(float2*)(Cf + (size_t)grow * DD + gcol)       = make_float2(v0, v1);
                *(float2*)(Cf + (size_t)(grow + 8) * DD + gcol) = make_float2(v2, v3);
                if (MODE == 4) {
                    colsum[j][0] += v0 + v2;
                    colsum[j][1] += v1 + v3;
                }
            }
            if (MODE == 1) {
                *(uint32_t*)(Ch + (size_t)grow * DD + gcol)       = pack_h2(v0, v1);
                *(uint32_t*)(Ch + (size_t)(grow + 8) * DD + gcol) = pack_h2(v2, v3);
            }
            if (MODE == 2) {
                const float* vb0 = aux2 + (size_t)(grow >> 12) * DD + gcol;
                v0 = fmaxf(v0 + vb0[0], 0.f);
                v1 = fmaxf(v1 + vb0[1], 0.f);
                v2 = fmaxf(v2 + vb0[0], 0.f);
                v3 = fmaxf(v3 + vb0[1], 0.f);
                *(uint32_t*)(Ch + (size_t)grow * DD + gcol)       = pack_h2(v0, v1);
                *(uint32_t*)(Ch + (size_t)(grow + 8) * DD + gcol) = pack_h2(v2, v3);
            }
            if (MODE == 3) {
                const float* rp0 = aux1 + (size_t)grow * DD + gcol;
                const float* rp1 = aux1 + (size_t)(grow + 8) * DD + gcol;
                v0 += rp0[0] + aux2[gcol];
                v1 += rp0[1] + aux2[gcol + 1];
                v2 += rp1[0] + aux2[gcol];
                v3 += rp1[1] + aux2[gcol + 1];
                *(float2*)(Cf + (size_t)grow * DD + gcol)       = make_float2(v0, v1);
                *(float2*)(Cf + (size_t)(grow + 8) * DD + gcol) = make_float2(v2, v3);
            }
        }
    }

    if (MODE == 4) {
        #pragma unroll
        for (int j = 0; j < 8; j++) {
            #pragma unroll
            for (int q = 0; q < 2; q++) {
                float s = colsum[j][q];
                s += __shfl_xor_sync(0xffffffffu, s, 4);
                s += __shfl_xor_sync(0xffffffffu, s, 8);
                s += __shfl_xor_sync(0xffffffffu, s, 16);
                colsum[j][q] = s;
            }
        }
        float* red = (float*)sm;     // [4][128]
        __syncthreads();
        if (lane < 4) {
            #pragma unroll
            for (int j = 0; j < 8; j++) {
                red[(wid & 3) * 128 + wn + j * 8 + lane * 2 + 0] = colsum[j][0];
                red[(wid & 3) * 128 + wn + j * 8 + lane * 2 + 1] = colsum[j][1];
            }
        }
        __syncthreads();
        if (tid < 128) {
            float s = red[tid] + red[128 + tid] + red[256 + tid] + red[384 + tid];
            int b = m0 >> 12, seg = (m0 >> 7) & (NSEG - 1);
            aux1[((size_t)b * NSEG + seg) * DD + n0 + tid] = s;
        }
    }
}

// ====== batched prep: 4 transposes + operator cvt + maxi reset ===========
__global__ void k_prep(const float* __restrict__ values, const float* __restrict__ ff1,
                       const float* __restrict__ ff2, const float* __restrict__ oper,
                       __half* __restrict__ valT, __half* __restrict__ f1tT,
                       __half* __restrict__ t1, __half* __restrict__ ff2T,
                       __half* __restrict__ operh, int* __restrict__ maxi) {
    int z = blockIdx.z;
    int c0 = blockIdx.x * 32, r0 = blockIdx.y * 32;
    int x = threadIdx.x, y = threadIdx.y;
    if (z == 4) {
        if (blockIdx.x == 0 && blockIdx.y == 0) {
            int flat = y * 32 + x;
            if (flat < BB * HH) maxi[flat] = INT_MIN;
        }
        #pragma unroll
        for (int j = 0; j < 32; j += 8) {
            size_t idx = (size_t)(r0 + y + j) * DD + c0 + x;
            operh[idx] = __float2half_rn(oper[idx]);
        }
        return;
    }
    const float* src = (z == 0) ? values : (z == 1) ? ff1
                      : (z == 2) ? (ff1 + (size_t)DD * DD) : ff2;
    __half* dst = (z == 0) ? valT : (z == 1) ? f1tT : (z == 2) ? t1 : ff2T;
    __shared__ float t[32][33];
    #pragma unroll
    for (int j = 0; j < 32; j += 8)
        t[y + j][x] = src[(size_t)(r0 + y + j) * DD + c0 + x];
    __syncthreads();
    #pragma unroll
    for (int j = 0; j < 32; j += 8)
        dst[(size_t)(c0 + y + j) * DD + r0 + x] = __float2half_rn(t[x][y + j]);
}

// =================== vb = vector @ ff1_bot + b1 (half t1) ================
__global__ void k_vb(const float* __restrict__ vec, const __half* __restrict__ t1,
                     const float* __restrict__ bias, float* __restrict__ vb) {
    __shared__ float sv[DD];
    int b = blockIdx.y;
    for (int i = threadIdx.x; i < DD; i += 256) sv[i] = vec[(size_t)b * DD + i];
    __syncthreads();
    int d = blockIdx.x * 256 + threadIdx.x;
    const __half2* tp = (const __half2*)(t1 + (size_t)d * DD);
    float s = 0.f;
    #pragma unroll 4
    for (int i = 0; i < DD / 2; i++) {
        float2 a = __half22float2(tp[i]);
        s += a.x * sv[2 * i] + a.y * sv[2 * i + 1];
    }
    vb[(size_t)b * DD + d] = s + bias[d];
}

// ===== logits + half-cvt of inputs + per-(b,h) max via atomicMax =========
__global__ void k_logits(const float* __restrict__ inputs,
                         const float* __restrict__ W,
                         float* __restrict__ logits,
                         __half* __restrict__ inh,
                         int* __restrict__ maxi) {
    extern __shared__ float Wt[];   // [16][1024] + 16 ints tail
    int* smax = (int*)(Wt + DD * HH);
    int tid = threadIdx.x;
    if (tid < HH) smax[tid] = INT_MIN;
    for (int idx = tid; idx < DD * HH; idx += 256) {
        int i = idx >> 4, h = idx & 15;
        Wt[h * DD + i] = W[idx];
    }
    __syncthreads();
    int warp = tid >> 5, lane = tid & 31;
    float rowmax[HH];
    #pragma unroll
    for (int h = 0; h < HH; h++) rowmax[h] = -3.4e38f;
    for (int rr = 0; rr < 4; rr++) {
        int r = blockIdx.x * 32 + warp * 4 + rr;
        const float4* xp = (const float4*)(inputs + (size_t)r * DD);
        uint2* hp = (uint2*)(inh + (size_t)r * DD);
        float acc[HH];
        #pragma unroll
        for (int h = 0; h < HH; h++) acc[h] = 0.f;
        #pragma unroll
        for (int j = 0; j < 8; j++) {
            float4 x = xp[lane + 32 * j];
            hp[lane + 32 * j] = make_uint2(pack_h2(x.x, x.y), pack_h2(x.z, x.w));
            int i0 = (lane + 32 * j) * 4;
            #pragma unroll
            for (int h = 0; h < HH; h++) {
                float4 w = *(const float4*)&Wt[h * DD + i0];
                acc[h] += x.x * w.x + x.y * w.y + x.z * w.z + x.w * w.w;
            }
        }
        #pragma unroll
        for (int h = 0; h < HH; h++) {
            #pragma unroll
            for (int o = 16; o > 0; o >>= 1)
                acc[h] += __shfl_xor_sync(0xffffffffu, acc[h], o);
        }
        if (lane == 0) {
            #pragma unroll
            for (int h = 0; h < HH; h++) {
                logits[(size_t)r * HH + h] = acc[h];
                rowmax[h] = fmaxf(rowmax[h], acc[h]);
            }
        }
    }
    if (lane == 0) {
        #pragma unroll
        for (int h = 0; h < HH; h++) atomicMax(&smax[h], enc_f(rowmax[h]));
    }
    __syncthreads();
    if (tid < HH) {
        int b = (blockIdx.x * 32) >> 12;
        atomicMax(&maxi[b * HH + tid], smax[tid]);
    }
}

// ---------------- scans (scan1 fused into v-GEMM) -----------------------
#define DD4 (DD/4)
__global__ void k_scan2(float4* __restrict__ segsum) {
    int b = blockIdx.x, c = threadIdx.x;
    float4 run = make_float4(0.f, 0.f, 0.f, 0.f);
    for (int seg = 0; seg < NSEG; seg++) {
        size_t idx = ((size_t)b * NSEG + seg) * DD4 + c;
        float4 v = segsum[idx];
        segsum[idx] = run;
        run.x += v.x; run.y += v.y; run.z += v.z; run.w += v.w;
    }
}

// prefix + att scaling; computes att = exp((logit-max)*temp) inline
__global__ void k_scan3(const float4* __restrict__ V, const float4* __restrict__ segsum,
                        const float* __restrict__ logits, const int* __restrict__ maxi,
                        const float* __restrict__ temp, __half* __restrict__ out) {
    __shared__ float satt[SEG * 8];   // [s][h_local]
    int tx = threadIdx.x;             // 0..127
    int c = blockIdx.x * 128 + tx;    // float4 channel
    int seg = blockIdx.y, b = blockIdx.z;
    int h0 = blockIdx.x * 8;
    size_t base = (size_t)b * SS + (size_t)seg * SEG;

    {   // fill att tile: thread s = tx computes 8 heads
        const float* lp = logits + (base + tx) * HH + h0;
        float4 l0 = *(const float4*)lp;
        float4 l1 = *(const float4*)(lp + 4);
        float lv[8] = {l0.x, l0.y, l0.z, l0.w, l1.x, l1.y, l1.z, l1.w};
        #pragma unroll
        for (int q = 0; q < 8; q++) {
            float m = dec_f(maxi[b * HH + h0 + q]);
            satt[tx * 8 + q] = expf((lv[q] - m) * temp[h0 + q]);
        }
    }
    __syncthreads();

    int hl = tx >> 4;                 // local head index
    float4 run = segsum[((size_t)b * NSEG + seg) * DD4 + c];
    const float4* p = V + base * DD4 + c;
    __half* op = out + base * DD + c * 4;
    #pragma unroll 8
    for (int i = 0; i < SEG; i++) {
        float4 v = p[(size_t)i * DD4];
        run.x += v.x; run.y += v.y; run.z += v.z; run.w += v.w;
        float a = satt[i * 8 + hl];
        float cnt = (float)(seg * SEG + i + 1);
        float s = __fdividef(a, a * cnt + 1e-30f);
        *(uint32_t*)(op + (size_t)i * DD)     = pack_h2(run.x * s, run.y * s);
        *(uint32_t*)(op + (size_t)i * DD + 2) = pack_h2(run.z * s, run.w * s);
    }
}

// ---------------- LayerNorm (in place over d_out rows) ------------------
__global__ void k_ln(float* __restrict__ X, const float* __restrict__ g,
                     const float* __restrict__ be) {
    int r = blockIdx.x;
    float* p = X + (size_t)r * DD;
    int i = threadIdx.x * 4;
    float4 x = *(const float4*)(p + i);
    __shared__ float red[256];
    float s = x.x + x.y + x.z + x.w;
    red[threadIdx.x] = s; __syncthreads();
    for (int o = 128; o > 0; o >>= 1) {
        if (threadIdx.x < o) red[threadIdx.x] += red[threadIdx.x + o];
        __syncthreads();
    }
    float mean = red[0] * (1.f / DD);
    __syncthreads();
    float d0 = x.x - mean, d1 = x.y - mean, d2 = x.z - mean, d3 = x.w - mean;
    red[threadIdx.x] = d0 * d0 + d1 * d1 + d2 * d2 + d3 * d3;
    __syncthreads();
    for (int o = 128; o > 0; o >>= 1) {
        if (threadIdx.x < o) red[threadIdx.x] += red[threadIdx.x + o];
        __syncthreads();
    }
    float inv = rsqrtf(red[0] * (1.f / DD) + 1e-6f);
    float4 o4;
    o4.x = d0 * inv * g[i + 0] + be[i + 0];
    o4.y = d1 * inv * g[i + 1] + be[i + 1];
    o4.z = d2 * inv * g[i + 2] + be[i + 2];
    o4.w = d3 * inv * g[i + 3] + be[i + 3];
    *(float4*)(p + i) = o4;
}

// ---------------- launcher ----------------------------------------------
extern "C" void kernel_launch(void* const* d_in, const int* in_sizes, int n_in,
                              void* d_out, int out_size) {
    (void)in_sizes; (void)n_in; (void)out_size;
    const float* inputs   = (const float*)d_in[0];
    const float* vector   = (const float*)d_in[1];
    const float* attw     = (const float*)d_in[2];
    const float* temp     = (const float*)d_in[3];
    const float* values   = (const float*)d_in[4];
    const float* oper     = (const float*)d_in[5];
    const float* ff1      = (const float*)d_in[6];
    const float* ff1_bias = (const float*)d_in[7];
    const float* ff2      = (const float*)d_in[8];
    const float* ff2_bias = (const float*)d_in[9];
    const float* ln_gamma = (const float*)d_in[10];
    const float* ln_beta  = (const float*)d_in[11];
    float* out = (float*)d_out;

    float *logit_p, *v_p, *seg_p, *vb_p;
    int* maxi_p;
    __half *inh_p, *attnh_p, *h1h_p, *valT_p, *f1tT_p, *t1_p, *ff2T_p, *operh_p, *owT_p;
    cudaGetSymbolAddress((void**)&logit_p, g_logit);
    cudaGetSymbolAddress((void**)&maxi_p,  g_maxi);
    cudaGetSymbolAddress((void**)&v_p,     g_v);
    cudaGetSymbolAddress((void**)&seg_p,   g_seg);
    cudaGetSymbolAddress((void**)&vb_p,    g_vb);
    cudaGetSymbolAddress((void**)&inh_p,   g_in_h);
    cudaGetSymbolAddress((void**)&attnh_p, g_attn_h);
    cudaGetSymbolAddress((void**)&h1h_p,   g_h1h);
    cudaGetSymbolAddress((void**)&valT_p,  g_valTh);
    cudaGetSymbolAddress((void**)&f1tT_p,  g_f1tTh);
    cudaGetSymbolAddress((void**)&t1_p,    g_t1h);
    cudaGetSymbolAddress((void**)&ff2T_p,  g_ff2Th);
    cudaGetSymbolAddress((void**)&operh_p, g_operh);
    cudaGetSymbolAddress((void**)&owT_p,   g_owTh);

    cudaFuncSetAttribute(gemm_mma<1>, cudaFuncAttributeMaxDynamicSharedMemorySize, GEMM_SMEM);
    cudaFuncSetAttribute(gemm_mma<2>, cudaFuncAttributeMaxDynamicSharedMemorySize, GEMM_SMEM);
    cudaFuncSetAttribute(gemm_mma<3>, cudaFuncAttributeMaxDynamicSharedMemorySize, GEMM_SMEM);
    cudaFuncSetAttribute(gemm_mma<4>, cudaFuncAttributeMaxDynamicSharedMemorySize, GEMM_SMEM);
    cudaFuncSetAttribute(k_logits, cudaFuncAttributeMaxDynamicSharedMemorySize, 65536 + 64);

    // 0: batched prep (4 transposes + oper cvt + maxi reset)
    k_prep<<<dim3(32, 32, 5), dim3(32, 8)>>>(values, ff1, ff2, oper,
                                             valT_p, f1tT_p, t1_p, ff2T_p,
                                             operh_p, maxi_p);
    // 1: logits + half inputs + per-(b,h) max
    k_logits<<<MR / 32, 256, 65536 + 64>>>(inputs, attw, logit_p, inh_p, maxi_p);
    // 2: vb = vector @ ff1_bot + b1
    k_vb<<<dim3(DD / 256, BB), 256>>>(vector, t1_p, ff1_bias, vb_p);
    // 3: owT[n][f] = sum_dv t1[n][dv] * operator[f][dv]  (half out)
    gemm_mma<1><<<dim3(8, 8), 256, GEMM_SMEM>>>(t1_p, operh_p, nullptr, nullptr,
                                                owT_p, nullptr, nullptr);
    // 4: v = inputs @ values (fp32 out) + fused segment sums  <- ncu slot
    gemm_mma<4><<<dim3(8, MR / 128), 256, GEMM_SMEM>>>(inh_p, valT_p, nullptr, nullptr,
                                                       v_p, seg_p, nullptr);
    // 5: exclusive scan of segment sums
    k_scan2<<<BB, 256>>>((float4*)seg_p);
    // 6: prefix + att scaling -> half attn_out (att computed inline)
    dim3 scanGrid(2, NSEG, BB);
    k_scan3<<<scanGrid, 128>>>((const float4*)v_p, (const float4*)seg_p,
                               logit_p, maxi_p, temp, attnh_p);
    // 7: h1 = relu(inputs@ff1_top + attn@OW + vb)  (half out)
    gemm_mma<2><<<dim3(8, MR / 128), 256, GEMM_SMEM>>>(inh_p, f1tT_p, attnh_p, owT_p,
                                                       h1h_p, nullptr, vb_p);
    // 8: out = h1 @ ff2 + b2 + inputs (fp32)
    gemm_mma<3><<<dim3(8, MR / 128), 256, GEMM_SMEM>>>(h1h_p, ff2T_p, nullptr, nullptr,
                                                       out, (float*)inputs, ff2_bias);
    // 9: LayerNorm in place
    k_ln<<<MR, 256>>>(out, ln_gamma, ln_beta);
}